// round 1
// baseline (speedup 1.0000x reference)
#include <cuda_runtime.h>

#define NU 100000
#define NI 100000
#define DD 64
#define NL 3
#define NE 6400000
#define NB 16384
#define NN (NU + NI)

// Scratch (51.2 MB each) — __device__ globals, no allocation.
__device__ float g_emb[(size_t)NN * DD];   // current layer embeddings
__device__ float g_tmp[(size_t)NN * DD];   // SpMM output
__device__ float g_acc[(size_t)NN * DD];   // running sum over layers

__device__ __forceinline__ float sigmoidf(float x) {
    return 1.0f / (1.0f + __expf(-x));
}

// ---------------------------------------------------------------------------
// Layer-0 fusion: g_emb = concat(a0*user + (1-a0)*symptom, b0*item + (1-b0)*herb)
// g_acc = g_emb
// ---------------------------------------------------------------------------
__global__ void k_fuse0(const float* __restrict__ ue, const float* __restrict__ ie,
                        const float* __restrict__ se, const float* __restrict__ he,
                        const float* __restrict__ ulw, const float* __restrict__ ilw) {
    int idx = blockIdx.x * blockDim.x + threadIdx.x;      // float4 index
    const int n4 = NN * DD / 4;
    if (idx >= n4) return;
    float4 r;
    if (idx < NU * DD / 4) {
        float a = sigmoidf(ulw[0]);
        float4 x = ((const float4*)ue)[idx];
        float4 s = ((const float4*)se)[idx];
        r.x = a * x.x + (1.0f - a) * s.x;
        r.y = a * x.y + (1.0f - a) * s.y;
        r.z = a * x.z + (1.0f - a) * s.z;
        r.w = a * x.w + (1.0f - a) * s.w;
    } else {
        int j = idx - NU * DD / 4;
        float b = sigmoidf(ilw[0]);
        float4 x = ((const float4*)ie)[j];
        float4 h = ((const float4*)he)[j];
        r.x = b * x.x + (1.0f - b) * h.x;
        r.y = b * x.y + (1.0f - b) * h.y;
        r.z = b * x.z + (1.0f - b) * h.z;
        r.w = b * x.w + (1.0f - b) * h.w;
    }
    ((float4*)g_emb)[idx] = r;
    ((float4*)g_acc)[idx] = r;
}

// ---------------------------------------------------------------------------
// Zero the SpMM accumulator
// ---------------------------------------------------------------------------
__global__ void k_zero_tmp() {
    int idx = blockIdx.x * blockDim.x + threadIdx.x;
    const int n4 = NN * DD / 4;
    if (idx >= n4) return;
    ((float4*)g_tmp)[idx] = make_float4(0.f, 0.f, 0.f, 0.f);
}

// ---------------------------------------------------------------------------
// SpMM scatter: g_tmp[row] += val * g_emb[col]
// 16 threads per edge, each handles one float4 (16B) chunk of D=64.
// Consecutive threads of a warp cover one full 256B row (coalesced).
// ---------------------------------------------------------------------------
__global__ void k_scatter(const float* __restrict__ ev, const int* __restrict__ er,
                          const int* __restrict__ ec) {
    int tid = blockIdx.x * blockDim.x + threadIdx.x;
    if (tid >= NE * 16) return;
    int e = tid >> 4;
    int c = tid & 15;
    float v   = ev[e];
    int  col  = ec[e];
    int  row  = er[e];
    float4 x = ((const float4*)g_emb)[col * 16 + c];
    float* dst = &g_tmp[row * 64 + c * 4];
    atomicAdd(dst + 0, v * x.x);
    atomicAdd(dst + 1, v * x.y);
    atomicAdd(dst + 2, v * x.z);
    atomicAdd(dst + 3, v * x.w);
}

// ---------------------------------------------------------------------------
// Per-layer fusion: g_emb = fuse(g_tmp, symptom/herb, lw[layer]); g_acc += g_emb
// ---------------------------------------------------------------------------
__global__ void k_fuseL(const float* __restrict__ se, const float* __restrict__ he,
                        const float* __restrict__ ulw, const float* __restrict__ ilw,
                        int layer) {
    int idx = blockIdx.x * blockDim.x + threadIdx.x;
    const int n4 = NN * DD / 4;
    if (idx >= n4) return;
    float4 t = ((const float4*)g_tmp)[idx];
    float4 r;
    if (idx < NU * DD / 4) {
        float a = sigmoidf(ulw[layer]);
        float4 s = ((const float4*)se)[idx];
        r.x = a * t.x + (1.0f - a) * s.x;
        r.y = a * t.y + (1.0f - a) * s.y;
        r.z = a * t.z + (1.0f - a) * s.z;
        r.w = a * t.w + (1.0f - a) * s.w;
    } else {
        int j = idx - NU * DD / 4;
        float b = sigmoidf(ilw[layer]);
        float4 h = ((const float4*)he)[j];
        r.x = b * t.x + (1.0f - b) * h.x;
        r.y = b * t.y + (1.0f - b) * h.y;
        r.z = b * t.z + (1.0f - b) * h.z;
        r.w = b * t.w + (1.0f - b) * h.w;
    }
    ((float4*)g_emb)[idx] = r;
    float4 acc = ((float4*)g_acc)[idx];
    acc.x += r.x; acc.y += r.y; acc.z += r.z; acc.w += r.w;
    ((float4*)g_acc)[idx] = acc;
}

// ---------------------------------------------------------------------------
// Final: gamma[b] = dot(acc[users[b]], acc[U + items[b]]) / 16
// (light_out = acc/4, so dot of two light_out vectors = dot(acc,acc)/16)
// One warp per pair.
// ---------------------------------------------------------------------------
__global__ void k_dot(const int* __restrict__ users, const int* __restrict__ items,
                      float* __restrict__ out) {
    int w = (blockIdx.x * blockDim.x + threadIdx.x) >> 5;
    int l = threadIdx.x & 31;
    if (w >= NB) return;
    int u  = users[w];
    int it = items[w];
    const float* pu = &g_acc[(size_t)u * 64];
    const float* pi = &g_acc[(size_t)(NU + it) * 64];
    float s = pu[l] * pi[l] + pu[l + 32] * pi[l + 32];
    #pragma unroll
    for (int o = 16; o > 0; o >>= 1)
        s += __shfl_down_sync(0xffffffffu, s, o);
    if (l == 0) out[w] = s * (1.0f / 16.0f);
}

extern "C" void kernel_launch(void* const* d_in, const int* in_sizes, int n_in,
                              void* d_out, int out_size) {
    const float* user_emb    = (const float*)d_in[0];
    const float* item_emb    = (const float*)d_in[1];
    const float* symptom_emb = (const float*)d_in[2];
    const float* herb_emb    = (const float*)d_in[3];
    const float* user_lw     = (const float*)d_in[4];
    const float* item_lw     = (const float*)d_in[5];
    const float* edge_val    = (const float*)d_in[6];
    const int*   edge_row    = (const int*)d_in[7];
    const int*   edge_col    = (const int*)d_in[8];
    const int*   users       = (const int*)d_in[9];
    const int*   items       = (const int*)d_in[10];
    float* out = (float*)d_out;

    const int n4 = NN * DD / 4;                 // 3.2M float4 elements
    const int TB = 256;
    const int gElem = (n4 + TB - 1) / TB;       // elementwise grid
    const int gScat = (NE * 16 + TB - 1) / TB;  // scatter grid

    k_fuse0<<<gElem, TB>>>(user_emb, item_emb, symptom_emb, herb_emb, user_lw, item_lw);
    for (int layer = 1; layer <= NL; layer++) {
        k_zero_tmp<<<gElem, TB>>>();
        k_scatter<<<gScat, TB>>>(edge_val, edge_row, edge_col);
        k_fuseL<<<gElem, TB>>>(symptom_emb, herb_emb, user_lw, item_lw, layer);
    }
    k_dot<<<(NB * 32 + TB - 1) / TB, TB>>>(users, items, out);
}

// round 2
// speedup vs baseline: 1.9906x; 1.9906x over previous
#include <cuda_runtime.h>

#define NU 100000
#define NI 100000
#define DD 64
#define NL 3
#define NE 6400000
#define NB 16384
#define NN (NU + NI)

// Scratch (51.2 MB each) — __device__ globals, no allocation.
__device__ float g_emb[(size_t)NN * DD];   // current layer embeddings
__device__ float g_tmp[(size_t)NN * DD];   // SpMM output
__device__ float g_acc[(size_t)NN * DD];   // running sum over layers

__device__ __forceinline__ float sigmoidf(float x) {
    return 1.0f / (1.0f + __expf(-x));
}

__device__ __forceinline__ void red_add_v4(float* p, float a, float b, float c, float d) {
    asm volatile("red.global.add.v4.f32 [%0], {%1,%2,%3,%4};"
                 :: "l"(p), "f"(a), "f"(b), "f"(c), "f"(d) : "memory");
}

// ---------------------------------------------------------------------------
// Layer-0 fusion: g_emb = concat(a0*user+(1-a0)*symptom, b0*item+(1-b0)*herb)
// g_acc = g_emb; g_tmp = 0 (ready for first scatter)
// ---------------------------------------------------------------------------
__global__ void k_fuse0(const float* __restrict__ ue, const float* __restrict__ ie,
                        const float* __restrict__ se, const float* __restrict__ he,
                        const float* __restrict__ ulw, const float* __restrict__ ilw) {
    int idx = blockIdx.x * blockDim.x + threadIdx.x;      // float4 index
    const int n4 = NN * DD / 4;
    if (idx >= n4) return;
    float4 r;
    if (idx < NU * DD / 4) {
        float a = sigmoidf(ulw[0]);
        float4 x = ((const float4*)ue)[idx];
        float4 s = ((const float4*)se)[idx];
        r.x = a * x.x + (1.0f - a) * s.x;
        r.y = a * x.y + (1.0f - a) * s.y;
        r.z = a * x.z + (1.0f - a) * s.z;
        r.w = a * x.w + (1.0f - a) * s.w;
    } else {
        int j = idx - NU * DD / 4;
        float b = sigmoidf(ilw[0]);
        float4 x = ((const float4*)ie)[j];
        float4 h = ((const float4*)he)[j];
        r.x = b * x.x + (1.0f - b) * h.x;
        r.y = b * x.y + (1.0f - b) * h.y;
        r.z = b * x.z + (1.0f - b) * h.z;
        r.w = b * x.w + (1.0f - b) * h.w;
    }
    ((float4*)g_emb)[idx] = r;
    ((float4*)g_acc)[idx] = r;
    ((float4*)g_tmp)[idx] = make_float4(0.f, 0.f, 0.f, 0.f);
}

// ---------------------------------------------------------------------------
// SpMM scatter: g_tmp[row] += val * g_emb[col]
// 16 threads per edge, each handles one float4 (16B) chunk of D=64.
// One red.global.add.v4.f32 per thread.
// ---------------------------------------------------------------------------
__global__ void k_scatter(const float* __restrict__ ev, const int* __restrict__ er,
                          const int* __restrict__ ec) {
    long long tid = (long long)blockIdx.x * blockDim.x + threadIdx.x;
    if (tid >= (long long)NE * 16) return;
    int e = (int)(tid >> 4);
    int c = (int)(tid & 15);
    float v   = __ldg(&ev[e]);
    int  col  = __ldg(&ec[e]);
    int  row  = __ldg(&er[e]);
    float4 x = ((const float4*)g_emb)[col * 16 + c];
    float* dst = &g_tmp[(size_t)row * 64 + c * 4];
    red_add_v4(dst, v * x.x, v * x.y, v * x.z, v * x.w);
}

// ---------------------------------------------------------------------------
// Per-layer fusion: g_emb = fuse(g_tmp, symptom/herb, lw[layer]);
// g_acc += g_emb; g_tmp = 0 for next layer's scatter.
// ---------------------------------------------------------------------------
__global__ void k_fuseL(const float* __restrict__ se, const float* __restrict__ he,
                        const float* __restrict__ ulw, const float* __restrict__ ilw,
                        int layer) {
    int idx = blockIdx.x * blockDim.x + threadIdx.x;
    const int n4 = NN * DD / 4;
    if (idx >= n4) return;
    float4 t = ((const float4*)g_tmp)[idx];
    float4 r;
    if (idx < NU * DD / 4) {
        float a = sigmoidf(ulw[layer]);
        float4 s = ((const float4*)se)[idx];
        r.x = a * t.x + (1.0f - a) * s.x;
        r.y = a * t.y + (1.0f - a) * s.y;
        r.z = a * t.z + (1.0f - a) * s.z;
        r.w = a * t.w + (1.0f - a) * s.w;
    } else {
        int j = idx - NU * DD / 4;
        float b = sigmoidf(ilw[layer]);
        float4 h = ((const float4*)he)[j];
        r.x = b * t.x + (1.0f - b) * h.x;
        r.y = b * t.y + (1.0f - b) * h.y;
        r.z = b * t.z + (1.0f - b) * h.z;
        r.w = b * t.w + (1.0f - b) * h.w;
    }
    ((float4*)g_emb)[idx] = r;
    ((float4*)g_tmp)[idx] = make_float4(0.f, 0.f, 0.f, 0.f);
    float4 acc = ((float4*)g_acc)[idx];
    acc.x += r.x; acc.y += r.y; acc.z += r.z; acc.w += r.w;
    ((float4*)g_acc)[idx] = acc;
}

// ---------------------------------------------------------------------------
// Final: gamma[b] = dot(acc[users[b]], acc[U + items[b]]) / 16
// One warp per pair.
// ---------------------------------------------------------------------------
__global__ void k_dot(const int* __restrict__ users, const int* __restrict__ items,
                      float* __restrict__ out) {
    int w = (blockIdx.x * blockDim.x + threadIdx.x) >> 5;
    int l = threadIdx.x & 31;
    if (w >= NB) return;
    int u  = users[w];
    int it = items[w];
    const float* pu = &g_acc[(size_t)u * 64];
    const float* pi = &g_acc[(size_t)(NU + it) * 64];
    float s = pu[l] * pi[l] + pu[l + 32] * pi[l + 32];
    #pragma unroll
    for (int o = 16; o > 0; o >>= 1)
        s += __shfl_down_sync(0xffffffffu, s, o);
    if (l == 0) out[w] = s * (1.0f / 16.0f);
}

extern "C" void kernel_launch(void* const* d_in, const int* in_sizes, int n_in,
                              void* d_out, int out_size) {
    const float* user_emb    = (const float*)d_in[0];
    const float* item_emb    = (const float*)d_in[1];
    const float* symptom_emb = (const float*)d_in[2];
    const float* herb_emb    = (const float*)d_in[3];
    const float* user_lw     = (const float*)d_in[4];
    const float* item_lw     = (const float*)d_in[5];
    const float* edge_val    = (const float*)d_in[6];
    const int*   edge_row    = (const int*)d_in[7];
    const int*   edge_col    = (const int*)d_in[8];
    const int*   users       = (const int*)d_in[9];
    const int*   items       = (const int*)d_in[10];
    float* out = (float*)d_out;

    const int n4 = NN * DD / 4;                 // 3.2M float4 elements
    const int TB = 256;
    const int gElem = (n4 + TB - 1) / TB;       // elementwise grid
    const long long scatThreads = (long long)NE * 16;
    const int gScat = (int)((scatThreads + TB - 1) / TB);

    k_fuse0<<<gElem, TB>>>(user_emb, item_emb, symptom_emb, herb_emb, user_lw, item_lw);
    for (int layer = 1; layer <= NL; layer++) {
        k_scatter<<<gScat, TB>>>(edge_val, edge_row, edge_col);
        k_fuseL<<<gElem, TB>>>(symptom_emb, herb_emb, user_lw, item_lw, layer);
    }
    k_dot<<<(NB * 32 + TB - 1) / TB, TB>>>(users, items, out);
}

// round 3
// speedup vs baseline: 3.5830x; 1.7999x over previous
#include <cuda_runtime.h>

#define NU 100000
#define NI 100000
#define DD 64
#define NL 3
#define NE 6400000
#define NB 16384
#define NN (NU + NI)

#define SCAN_BS 512
#define SCAN_NBLK ((NN + SCAN_BS - 1) / SCAN_BS)   // 391

// Scratch — __device__ globals, no allocation.
__device__ float g_embA[(size_t)NN * DD];
__device__ float g_embB[(size_t)NN * DD];
__device__ float g_acc[(size_t)NN * DD];
__device__ int   g_count[NN];        // per-row edge counts
__device__ int   g_rowptr[NN + 1];   // CSR offsets
__device__ int   g_woff[NN];         // write cursors for placement
__device__ int   g_bsum[SCAN_NBLK];  // block partial sums for scan
__device__ int2  g_edges[NE];        // packed {col, val-bits} sorted by row

__device__ __forceinline__ float sigmoidf(float x) {
    return 1.0f / (1.0f + __expf(-x));
}

// ---------------------------------------------------------------------------
// Layer-0 fusion + zero row counters.
// g_embA = concat(a0*user+(1-a0)*symptom, b0*item+(1-b0)*herb); g_acc = g_embA
// ---------------------------------------------------------------------------
__global__ void k_fuse0(const float* __restrict__ ue, const float* __restrict__ ie,
                        const float* __restrict__ se, const float* __restrict__ he,
                        const float* __restrict__ ulw, const float* __restrict__ ilw) {
    int idx = blockIdx.x * blockDim.x + threadIdx.x;
    if (idx < NN) g_count[idx] = 0;
    const int n4 = NN * DD / 4;
    if (idx >= n4) return;
    float4 r;
    if (idx < NU * DD / 4) {
        float a = sigmoidf(ulw[0]);
        float4 x = ((const float4*)ue)[idx];
        float4 s = ((const float4*)se)[idx];
        r.x = a * x.x + (1.0f - a) * s.x;
        r.y = a * x.y + (1.0f - a) * s.y;
        r.z = a * x.z + (1.0f - a) * s.z;
        r.w = a * x.w + (1.0f - a) * s.w;
    } else {
        int j = idx - NU * DD / 4;
        float b = sigmoidf(ilw[0]);
        float4 x = ((const float4*)ie)[j];
        float4 h = ((const float4*)he)[j];
        r.x = b * x.x + (1.0f - b) * h.x;
        r.y = b * x.y + (1.0f - b) * h.y;
        r.z = b * x.z + (1.0f - b) * h.z;
        r.w = b * x.w + (1.0f - b) * h.w;
    }
    ((float4*)g_embA)[idx] = r;
    ((float4*)g_acc)[idx] = r;
}

// ---------------------------------------------------------------------------
// CSR build step 1: histogram of rows
// ---------------------------------------------------------------------------
__global__ void k_count(const int* __restrict__ er) {
    int e = blockIdx.x * blockDim.x + threadIdx.x;
    if (e >= NE) return;
    atomicAdd(&g_count[er[e]], 1);
}

// ---------------------------------------------------------------------------
// CSR build step 2a: per-block exclusive scan of counts
// ---------------------------------------------------------------------------
__global__ void k_scan_blocks() {
    __shared__ int sh[SCAN_BS];
    int i = blockIdx.x * SCAN_BS + threadIdx.x;
    int v = (i < NN) ? g_count[i] : 0;
    sh[threadIdx.x] = v;
    __syncthreads();
    // Hillis-Steele inclusive scan
    #pragma unroll
    for (int o = 1; o < SCAN_BS; o <<= 1) {
        int t = (threadIdx.x >= o) ? sh[threadIdx.x - o] : 0;
        __syncthreads();
        sh[threadIdx.x] += t;
        __syncthreads();
    }
    if (i < NN) g_rowptr[i] = sh[threadIdx.x] - v;   // exclusive
    if (threadIdx.x == SCAN_BS - 1) g_bsum[blockIdx.x] = sh[SCAN_BS - 1];
}

// ---------------------------------------------------------------------------
// CSR build step 2b: scan the block totals (single block)
// ---------------------------------------------------------------------------
__global__ void k_scan_tops() {
    __shared__ int sh[SCAN_BS];
    int v = (threadIdx.x < SCAN_NBLK) ? g_bsum[threadIdx.x] : 0;
    sh[threadIdx.x] = v;
    __syncthreads();
    #pragma unroll
    for (int o = 1; o < SCAN_BS; o <<= 1) {
        int t = (threadIdx.x >= o) ? sh[threadIdx.x - o] : 0;
        __syncthreads();
        sh[threadIdx.x] += t;
        __syncthreads();
    }
    if (threadIdx.x < SCAN_NBLK) g_bsum[threadIdx.x] = sh[threadIdx.x] - v;  // exclusive
}

// ---------------------------------------------------------------------------
// CSR build step 2c: add block offsets; init write cursors
// ---------------------------------------------------------------------------
__global__ void k_scan_add() {
    int i = blockIdx.x * blockDim.x + threadIdx.x;
    if (i >= NN) return;
    int p = g_rowptr[i] + g_bsum[i / SCAN_BS];
    g_rowptr[i] = p;
    g_woff[i] = p;
    if (i == 0) g_rowptr[NN] = NE;
}

// ---------------------------------------------------------------------------
// CSR build step 3: place packed {col, val} records into row buckets
// ---------------------------------------------------------------------------
__global__ void k_place(const float* __restrict__ ev, const int* __restrict__ er,
                        const int* __restrict__ ec) {
    int e = blockIdx.x * blockDim.x + threadIdx.x;
    if (e >= NE) return;
    int row = er[e];
    int pos = atomicAdd(&g_woff[row], 1);
    g_edges[pos] = make_int2(ec[e], __float_as_int(ev[e]));
}

// ---------------------------------------------------------------------------
// Gather SpMM + per-layer fusion + accumulate, no atomics.
// 16 threads per row (one float4 chunk each). pp selects ping-pong direction.
// ---------------------------------------------------------------------------
__global__ void k_spmm_fuse(const float* __restrict__ se, const float* __restrict__ he,
                            const float* __restrict__ ulw, const float* __restrict__ ilw,
                            int layer, int pp) {
    int tid = blockIdx.x * blockDim.x + threadIdx.x;
    int row = tid >> 4;
    int c   = tid & 15;
    if (row >= NN) return;

    const float4* cur  = (const float4*)(pp ? g_embB : g_embA);
    float4*       next = (float4*)(pp ? g_embA : g_embB);

    int s = __ldg(&g_rowptr[row]);
    int t = __ldg(&g_rowptr[row + 1]);

    float4 sum = make_float4(0.f, 0.f, 0.f, 0.f);
    int e = s;
    for (; e + 4 <= t; e += 4) {
        int2 e0 = __ldg(&g_edges[e + 0]);
        int2 e1 = __ldg(&g_edges[e + 1]);
        int2 e2 = __ldg(&g_edges[e + 2]);
        int2 e3 = __ldg(&g_edges[e + 3]);
        float4 x0 = __ldg(&cur[e0.x * 16 + c]);
        float4 x1 = __ldg(&cur[e1.x * 16 + c]);
        float4 x2 = __ldg(&cur[e2.x * 16 + c]);
        float4 x3 = __ldg(&cur[e3.x * 16 + c]);
        float v0 = __int_as_float(e0.y), v1 = __int_as_float(e1.y);
        float v2 = __int_as_float(e2.y), v3 = __int_as_float(e3.y);
        sum.x += v0 * x0.x + v1 * x1.x + v2 * x2.x + v3 * x3.x;
        sum.y += v0 * x0.y + v1 * x1.y + v2 * x2.y + v3 * x3.y;
        sum.z += v0 * x0.z + v1 * x1.z + v2 * x2.z + v3 * x3.z;
        sum.w += v0 * x0.w + v1 * x1.w + v2 * x2.w + v3 * x3.w;
    }
    for (; e < t; e++) {
        int2 ed = __ldg(&g_edges[e]);
        float4 x = __ldg(&cur[ed.x * 16 + c]);
        float v = __int_as_float(ed.y);
        sum.x += v * x.x; sum.y += v * x.y;
        sum.z += v * x.z; sum.w += v * x.w;
    }

    bool isU = row < NU;
    float w = sigmoidf(isU ? ulw[layer] : ilw[layer]);
    float4 sd = isU ? ((const float4*)se)[row * 16 + c]
                    : ((const float4*)he)[(row - NU) * 16 + c];
    float4 r;
    r.x = w * sum.x + (1.0f - w) * sd.x;
    r.y = w * sum.y + (1.0f - w) * sd.y;
    r.z = w * sum.z + (1.0f - w) * sd.z;
    r.w = w * sum.w + (1.0f - w) * sd.w;

    next[row * 16 + c] = r;
    float4 a = ((float4*)g_acc)[row * 16 + c];
    a.x += r.x; a.y += r.y; a.z += r.z; a.w += r.w;
    ((float4*)g_acc)[row * 16 + c] = a;
}

// ---------------------------------------------------------------------------
// Final: gamma[b] = dot(acc[users[b]], acc[U + items[b]]) / 16
// ---------------------------------------------------------------------------
__global__ void k_dot(const int* __restrict__ users, const int* __restrict__ items,
                      float* __restrict__ out) {
    int w = (blockIdx.x * blockDim.x + threadIdx.x) >> 5;
    int l = threadIdx.x & 31;
    if (w >= NB) return;
    int u  = users[w];
    int it = items[w];
    const float* pu = &g_acc[(size_t)u * 64];
    const float* pi = &g_acc[(size_t)(NU + it) * 64];
    float s = pu[l] * pi[l] + pu[l + 32] * pi[l + 32];
    #pragma unroll
    for (int o = 16; o > 0; o >>= 1)
        s += __shfl_down_sync(0xffffffffu, s, o);
    if (l == 0) out[w] = s * (1.0f / 16.0f);
}

extern "C" void kernel_launch(void* const* d_in, const int* in_sizes, int n_in,
                              void* d_out, int out_size) {
    const float* user_emb    = (const float*)d_in[0];
    const float* item_emb    = (const float*)d_in[1];
    const float* symptom_emb = (const float*)d_in[2];
    const float* herb_emb    = (const float*)d_in[3];
    const float* user_lw     = (const float*)d_in[4];
    const float* item_lw     = (const float*)d_in[5];
    const float* edge_val    = (const float*)d_in[6];
    const int*   edge_row    = (const int*)d_in[7];
    const int*   edge_col    = (const int*)d_in[8];
    const int*   users       = (const int*)d_in[9];
    const int*   items       = (const int*)d_in[10];
    float* out = (float*)d_out;

    const int n4 = NN * DD / 4;
    const int TB = 256;
    const int gElem = (n4 + TB - 1) / TB;
    const int gEdge = (NE + TB - 1) / TB;
    const int gRow  = (NN * 16 + TB - 1) / TB;

    k_fuse0<<<gElem, TB>>>(user_emb, item_emb, symptom_emb, herb_emb, user_lw, item_lw);
    k_count<<<gEdge, TB>>>(edge_row);
    k_scan_blocks<<<SCAN_NBLK, SCAN_BS>>>();
    k_scan_tops<<<1, SCAN_BS>>>();
    k_scan_add<<<(NN + TB - 1) / TB, TB>>>();
    k_place<<<gEdge, TB>>>(edge_val, edge_row, edge_col);

    for (int layer = 1; layer <= NL; layer++) {
        k_spmm_fuse<<<gRow, TB>>>(symptom_emb, herb_emb, user_lw, item_lw,
                                  layer, (layer - 1) & 1);
    }
    k_dot<<<(NB * 32 + TB - 1) / TB, TB>>>(users, items, out);
}

// round 5
// speedup vs baseline: 5.7705x; 1.6105x over previous
#include <cuda_runtime.h>
#include <cuda_fp16.h>

#define NU 100000
#define NI 100000
#define DD 64
#define NL 3
#define NE 6400000
#define NB 16384
#define NN (NU + NI)

#define SCAN_BS 512
#define SCAN_NBLK ((NN + SCAN_BS - 1) / SCAN_BS)   // 391

// Scratch — __device__ globals, no allocation.
__device__ __half g_embA[(size_t)NN * DD];   // fp16 ping
__device__ __half g_embB[(size_t)NN * DD];   // fp16 pong
__device__ float  g_acc[(size_t)NN * DD];    // fp32 running sum
__device__ int    g_count[NN];
__device__ int    g_rowptr[NN + 1];
__device__ int    g_woff[NN];
__device__ int    g_bsum[SCAN_NBLK];
__device__ int2   g_edges[NE];               // packed {col, val-bits}

__device__ __forceinline__ float sigmoidf(float x) {
    return 1.0f / (1.0f + __expf(-x));
}

__device__ __forceinline__ unsigned int h2_to_u(__half2 h) {
    return *reinterpret_cast<unsigned int*>(&h);
}
__device__ __forceinline__ __half2 u_to_h2(unsigned int u) {
    return *reinterpret_cast<__half2*>(&u);
}

// ---------------------------------------------------------------------------
// Layer-0 fusion + zero row counters.
// g_embA(fp16) = fused layer-0; g_acc(fp32) = same (exact)
// ---------------------------------------------------------------------------
__global__ void k_fuse0(const float* __restrict__ ue, const float* __restrict__ ie,
                        const float* __restrict__ se, const float* __restrict__ he,
                        const float* __restrict__ ulw, const float* __restrict__ ilw) {
    int idx = blockIdx.x * blockDim.x + threadIdx.x;
    if (idx < NN) g_count[idx] = 0;
    const int n4 = NN * DD / 4;
    if (idx >= n4) return;
    float4 r;
    if (idx < NU * DD / 4) {
        float a = sigmoidf(ulw[0]);
        float4 x = ((const float4*)ue)[idx];
        float4 s = ((const float4*)se)[idx];
        r.x = a * x.x + (1.0f - a) * s.x;
        r.y = a * x.y + (1.0f - a) * s.y;
        r.z = a * x.z + (1.0f - a) * s.z;
        r.w = a * x.w + (1.0f - a) * s.w;
    } else {
        int j = idx - NU * DD / 4;
        float b = sigmoidf(ilw[0]);
        float4 x = ((const float4*)ie)[j];
        float4 h = ((const float4*)he)[j];
        r.x = b * x.x + (1.0f - b) * h.x;
        r.y = b * x.y + (1.0f - b) * h.y;
        r.z = b * x.z + (1.0f - b) * h.z;
        r.w = b * x.w + (1.0f - b) * h.w;
    }
    uint2 hp;
    hp.x = h2_to_u(__floats2half2_rn(r.x, r.y));
    hp.y = h2_to_u(__floats2half2_rn(r.z, r.w));
    ((uint2*)g_embA)[idx] = hp;
    ((float4*)g_acc)[idx] = r;
}

// ---------------------------------------------------------------------------
// CSR build
// ---------------------------------------------------------------------------
__global__ void k_count(const int* __restrict__ er) {
    int e = blockIdx.x * blockDim.x + threadIdx.x;
    if (e >= NE) return;
    atomicAdd(&g_count[er[e]], 1);
}

__global__ void k_scan_blocks() {
    __shared__ int sh[SCAN_BS];
    int i = blockIdx.x * SCAN_BS + threadIdx.x;
    int v = (i < NN) ? g_count[i] : 0;
    sh[threadIdx.x] = v;
    __syncthreads();
    #pragma unroll
    for (int o = 1; o < SCAN_BS; o <<= 1) {
        int t = (threadIdx.x >= o) ? sh[threadIdx.x - o] : 0;
        __syncthreads();
        sh[threadIdx.x] += t;
        __syncthreads();
    }
    if (i < NN) g_rowptr[i] = sh[threadIdx.x] - v;
    if (threadIdx.x == SCAN_BS - 1) g_bsum[blockIdx.x] = sh[SCAN_BS - 1];
}

__global__ void k_scan_tops() {
    __shared__ int sh[SCAN_BS];
    int v = (threadIdx.x < SCAN_NBLK) ? g_bsum[threadIdx.x] : 0;
    sh[threadIdx.x] = v;
    __syncthreads();
    #pragma unroll
    for (int o = 1; o < SCAN_BS; o <<= 1) {
        int t = (threadIdx.x >= o) ? sh[threadIdx.x - o] : 0;
        __syncthreads();
        sh[threadIdx.x] += t;
        __syncthreads();
    }
    if (threadIdx.x < SCAN_NBLK) g_bsum[threadIdx.x] = sh[threadIdx.x] - v;
}

__global__ void k_scan_add() {
    int i = blockIdx.x * blockDim.x + threadIdx.x;
    if (i >= NN) return;
    int p = g_rowptr[i] + g_bsum[i / SCAN_BS];
    g_rowptr[i] = p;
    g_woff[i] = p;
    if (i == 0) g_rowptr[NN] = NE;
}

__global__ void k_place(const float* __restrict__ ev, const int* __restrict__ er,
                        const int* __restrict__ ec) {
    int e = blockIdx.x * blockDim.x + threadIdx.x;
    if (e >= NE) return;
    int row = er[e];
    int pos = atomicAdd(&g_woff[row], 1);
    g_edges[pos] = make_int2(ec[e], __float_as_int(ev[e]));
}

// ---------------------------------------------------------------------------
// Gather SpMM (fp16 table, fp32 accumulate) + per-layer fusion + accumulate.
// 8 threads per row; each handles 8 consecutive dims (one 16B load per edge).
// ---------------------------------------------------------------------------
__global__ void k_spmm_fuse(const float* __restrict__ se, const float* __restrict__ he,
                            const float* __restrict__ ulw, const float* __restrict__ ilw,
                            int layer, int pp) {
    int tid = blockIdx.x * blockDim.x + threadIdx.x;
    int row = tid >> 3;
    int c   = tid & 7;
    if (row >= NN) return;

    const uint4* cur  = (const uint4*)(pp ? g_embB : g_embA);
    uint4*       next = (uint4*)(pp ? g_embA : g_embB);

    int s = __ldg(&g_rowptr[row]);
    int t = __ldg(&g_rowptr[row + 1]);

    float2 s0 = make_float2(0.f, 0.f), s1 = s0, s2 = s0, s3 = s0;

    int e = s;
    for (; e + 4 <= t; e += 4) {
        int2 e0 = __ldg(&g_edges[e + 0]);
        int2 e1 = __ldg(&g_edges[e + 1]);
        int2 e2 = __ldg(&g_edges[e + 2]);
        int2 e3 = __ldg(&g_edges[e + 3]);
        uint4 x0 = __ldg(&cur[e0.x * 8 + c]);
        uint4 x1 = __ldg(&cur[e1.x * 8 + c]);
        uint4 x2 = __ldg(&cur[e2.x * 8 + c]);
        uint4 x3 = __ldg(&cur[e3.x * 8 + c]);
        float v0 = __int_as_float(e0.y), v1 = __int_as_float(e1.y);
        float v2 = __int_as_float(e2.y), v3 = __int_as_float(e3.y);
        {
            float2 f;
            f = __half22float2(u_to_h2(x0.x)); s0.x += v0*f.x; s0.y += v0*f.y;
            f = __half22float2(u_to_h2(x0.y)); s1.x += v0*f.x; s1.y += v0*f.y;
            f = __half22float2(u_to_h2(x0.z)); s2.x += v0*f.x; s2.y += v0*f.y;
            f = __half22float2(u_to_h2(x0.w)); s3.x += v0*f.x; s3.y += v0*f.y;
            f = __half22float2(u_to_h2(x1.x)); s0.x += v1*f.x; s0.y += v1*f.y;
            f = __half22float2(u_to_h2(x1.y)); s1.x += v1*f.x; s1.y += v1*f.y;
            f = __half22float2(u_to_h2(x1.z)); s2.x += v1*f.x; s2.y += v1*f.y;
            f = __half22float2(u_to_h2(x1.w)); s3.x += v1*f.x; s3.y += v1*f.y;
            f = __half22float2(u_to_h2(x2.x)); s0.x += v2*f.x; s0.y += v2*f.y;
            f = __half22float2(u_to_h2(x2.y)); s1.x += v2*f.x; s1.y += v2*f.y;
            f = __half22float2(u_to_h2(x2.z)); s2.x += v2*f.x; s2.y += v2*f.y;
            f = __half22float2(u_to_h2(x2.w)); s3.x += v2*f.x; s3.y += v2*f.y;
            f = __half22float2(u_to_h2(x3.x)); s0.x += v3*f.x; s0.y += v3*f.y;
            f = __half22float2(u_to_h2(x3.y)); s1.x += v3*f.x; s1.y += v3*f.y;
            f = __half22float2(u_to_h2(x3.z)); s2.x += v3*f.x; s2.y += v3*f.y;
            f = __half22float2(u_to_h2(x3.w)); s3.x += v3*f.x; s3.y += v3*f.y;
        }
    }
    for (; e < t; e++) {
        int2 ed = __ldg(&g_edges[e]);
        uint4 x = __ldg(&cur[ed.x * 8 + c]);
        float v = __int_as_float(ed.y);
        float2 f;
        f = __half22float2(u_to_h2(x.x)); s0.x += v*f.x; s0.y += v*f.y;
        f = __half22float2(u_to_h2(x.y)); s1.x += v*f.x; s1.y += v*f.y;
        f = __half22float2(u_to_h2(x.z)); s2.x += v*f.x; s2.y += v*f.y;
        f = __half22float2(u_to_h2(x.w)); s3.x += v*f.x; s3.y += v*f.y;
    }

    bool isU = row < NU;
    float w = sigmoidf(isU ? ulw[layer] : ilw[layer]);
    float omw = 1.0f - w;
    // side embedding: 8 consecutive dims starting at c*8 (two float4 loads)
    const float4* sdp = isU ? (const float4*)se + (size_t)row * 16 + c * 2
                            : (const float4*)he + (size_t)(row - NU) * 16 + c * 2;
    float4 sa = __ldg(sdp);
    float4 sb = __ldg(sdp + 1);

    float r0 = w * s0.x + omw * sa.x;
    float r1 = w * s0.y + omw * sa.y;
    float r2 = w * s1.x + omw * sa.z;
    float r3 = w * s1.y + omw * sa.w;
    float r4 = w * s2.x + omw * sb.x;
    float r5 = w * s2.y + omw * sb.y;
    float r6 = w * s3.x + omw * sb.z;
    float r7 = w * s3.y + omw * sb.w;

    uint4 hout;
    hout.x = h2_to_u(__floats2half2_rn(r0, r1));
    hout.y = h2_to_u(__floats2half2_rn(r2, r3));
    hout.z = h2_to_u(__floats2half2_rn(r4, r5));
    hout.w = h2_to_u(__floats2half2_rn(r6, r7));
    next[row * 8 + c] = hout;

    float4* accp = (float4*)g_acc + (size_t)row * 16 + c * 2;
    float4 a0 = accp[0], a1 = accp[1];
    a0.x += r0; a0.y += r1; a0.z += r2; a0.w += r3;
    a1.x += r4; a1.y += r5; a1.z += r6; a1.w += r7;
    accp[0] = a0; accp[1] = a1;
}

// ---------------------------------------------------------------------------
// Final: gamma[b] = dot(acc[users[b]], acc[U + items[b]]) / 16
// ---------------------------------------------------------------------------
__global__ void k_dot(const int* __restrict__ users, const int* __restrict__ items,
                      float* __restrict__ out) {
    int w = (blockIdx.x * blockDim.x + threadIdx.x) >> 5;
    int l = threadIdx.x & 31;
    if (w >= NB) return;
    int u  = users[w];
    int it = items[w];
    const float* pu = &g_acc[(size_t)u * 64];
    const float* pi = &g_acc[(size_t)(NU + it) * 64];
    float s = pu[l] * pi[l] + pu[l + 32] * pi[l + 32];
    #pragma unroll
    for (int o = 16; o > 0; o >>= 1)
        s += __shfl_down_sync(0xffffffffu, s, o);
    if (l == 0) out[w] = s * (1.0f / 16.0f);
}

extern "C" void kernel_launch(void* const* d_in, const int* in_sizes, int n_in,
                              void* d_out, int out_size) {
    const float* user_emb    = (const float*)d_in[0];
    const float* item_emb    = (const float*)d_in[1];
    const float* symptom_emb = (const float*)d_in[2];
    const float* herb_emb    = (const float*)d_in[3];
    const float* user_lw     = (const float*)d_in[4];
    const float* item_lw     = (const float*)d_in[5];
    const float* edge_val    = (const float*)d_in[6];
    const int*   edge_row    = (const int*)d_in[7];
    const int*   edge_col    = (const int*)d_in[8];
    const int*   users       = (const int*)d_in[9];
    const int*   items       = (const int*)d_in[10];
    float* out = (float*)d_out;

    const int n4 = NN * DD / 4;
    const int TB = 256;
    const int gElem = (n4 + TB - 1) / TB;
    const int gEdge = (NE + TB - 1) / TB;
    const int gRow  = (NN * 8 + TB - 1) / TB;

    k_fuse0<<<gElem, TB>>>(user_emb, item_emb, symptom_emb, herb_emb, user_lw, item_lw);
    k_count<<<gEdge, TB>>>(edge_row);
    k_scan_blocks<<<SCAN_NBLK, SCAN_BS>>>();
    k_scan_tops<<<1, SCAN_BS>>>();
    k_scan_add<<<(NN + TB - 1) / TB, TB>>>();
    k_place<<<gEdge, TB>>>(edge_val, edge_row, edge_col);

    for (int layer = 1; layer <= NL; layer++) {
        k_spmm_fuse<<<gRow, TB>>>(symptom_emb, herb_emb, user_lw, item_lw,
                                  layer, (layer - 1) & 1);
    }
    k_dot<<<(NB * 32 + TB - 1) / TB, TB>>>(users, items, out);
}

// round 6
// speedup vs baseline: 6.8522x; 1.1875x over previous
#include <cuda_runtime.h>
#include <cuda_fp16.h>

#define NU 100000
#define NI 100000
#define DD 64
#define NL 3
#define NE 6400000
#define NB 16384
#define NN (NU + NI)

#define SCAN_BS 512
#define SCAN_NBLK ((NN + SCAN_BS - 1) / SCAN_BS)   // 391

// Scratch — __device__ globals, no allocation.
__device__ __half g_embs[NL + 1][(size_t)NN * DD];  // fp16 per-layer outputs
__device__ int    g_count[NN];
__device__ int    g_rowptr[NN + 1];
__device__ int    g_woff[NN];
__device__ int    g_bsum[SCAN_NBLK];
__device__ int2   g_edges[NE];                      // packed {col, val-bits}

__device__ __forceinline__ float sigmoidf(float x) {
    return 1.0f / (1.0f + __expf(-x));
}

__device__ __forceinline__ unsigned int h2_to_u(__half2 h) {
    return *reinterpret_cast<unsigned int*>(&h);
}
__device__ __forceinline__ __half2 u_to_h2(unsigned int u) {
    return *reinterpret_cast<__half2*>(&u);
}

// ---------------------------------------------------------------------------
// Layer-0 fusion + zero row counters. g_embs[0](fp16) = fused layer-0.
// ---------------------------------------------------------------------------
__global__ void k_fuse0(const float* __restrict__ ue, const float* __restrict__ ie,
                        const float* __restrict__ se, const float* __restrict__ he,
                        const float* __restrict__ ulw, const float* __restrict__ ilw) {
    int idx = blockIdx.x * blockDim.x + threadIdx.x;
    if (idx < NN) g_count[idx] = 0;
    const int n4 = NN * DD / 4;
    if (idx >= n4) return;
    float4 r;
    if (idx < NU * DD / 4) {
        float a = sigmoidf(ulw[0]);
        float4 x = ((const float4*)ue)[idx];
        float4 s = ((const float4*)se)[idx];
        r.x = a * x.x + (1.0f - a) * s.x;
        r.y = a * x.y + (1.0f - a) * s.y;
        r.z = a * x.z + (1.0f - a) * s.z;
        r.w = a * x.w + (1.0f - a) * s.w;
    } else {
        int j = idx - NU * DD / 4;
        float b = sigmoidf(ilw[0]);
        float4 x = ((const float4*)ie)[j];
        float4 h = ((const float4*)he)[j];
        r.x = b * x.x + (1.0f - b) * h.x;
        r.y = b * x.y + (1.0f - b) * h.y;
        r.z = b * x.z + (1.0f - b) * h.z;
        r.w = b * x.w + (1.0f - b) * h.w;
    }
    uint2 hp;
    hp.x = h2_to_u(__floats2half2_rn(r.x, r.y));
    hp.y = h2_to_u(__floats2half2_rn(r.z, r.w));
    ((uint2*)g_embs[0])[idx] = hp;
}

// ---------------------------------------------------------------------------
// CSR build
// ---------------------------------------------------------------------------
__global__ void k_count(const int* __restrict__ er) {
    int e = blockIdx.x * blockDim.x + threadIdx.x;
    if (e >= NE) return;
    atomicAdd(&g_count[er[e]], 1);
}

__global__ void k_scan_blocks() {
    __shared__ int sh[SCAN_BS];
    int i = blockIdx.x * SCAN_BS + threadIdx.x;
    int v = (i < NN) ? g_count[i] : 0;
    sh[threadIdx.x] = v;
    __syncthreads();
    #pragma unroll
    for (int o = 1; o < SCAN_BS; o <<= 1) {
        int t = (threadIdx.x >= o) ? sh[threadIdx.x - o] : 0;
        __syncthreads();
        sh[threadIdx.x] += t;
        __syncthreads();
    }
    if (i < NN) g_rowptr[i] = sh[threadIdx.x] - v;
    if (threadIdx.x == SCAN_BS - 1) g_bsum[blockIdx.x] = sh[SCAN_BS - 1];
}

__global__ void k_scan_tops() {
    __shared__ int sh[SCAN_BS];
    int v = (threadIdx.x < SCAN_NBLK) ? g_bsum[threadIdx.x] : 0;
    sh[threadIdx.x] = v;
    __syncthreads();
    #pragma unroll
    for (int o = 1; o < SCAN_BS; o <<= 1) {
        int t = (threadIdx.x >= o) ? sh[threadIdx.x - o] : 0;
        __syncthreads();
        sh[threadIdx.x] += t;
        __syncthreads();
    }
    if (threadIdx.x < SCAN_NBLK) g_bsum[threadIdx.x] = sh[threadIdx.x] - v;
}

__global__ void k_scan_add() {
    int i = blockIdx.x * blockDim.x + threadIdx.x;
    if (i >= NN) return;
    int p = g_rowptr[i] + g_bsum[i / SCAN_BS];
    g_rowptr[i] = p;
    g_woff[i] = p;
    if (i == 0) g_rowptr[NN] = NE;
}

__global__ void k_place(const float* __restrict__ ev, const int* __restrict__ er,
                        const int* __restrict__ ec) {
    int e = blockIdx.x * blockDim.x + threadIdx.x;
    if (e >= NE) return;
    int row = er[e];
    int pos = atomicAdd(&g_woff[row], 1);
    g_edges[pos] = make_int2(ec[e], __float_as_int(ev[e]));
}

// ---------------------------------------------------------------------------
// Gather SpMM (fp16 table, fp32 accumulate) + per-layer fusion.
// Reads g_embs[layer-1], writes g_embs[layer]. No accumulator traffic.
// 8 threads per row; each handles 8 consecutive dims (one 16B load per edge).
// ---------------------------------------------------------------------------
__global__ void k_spmm_fuse(const float* __restrict__ se, const float* __restrict__ he,
                            const float* __restrict__ ulw, const float* __restrict__ ilw,
                            int layer) {
    int tid = blockIdx.x * blockDim.x + threadIdx.x;
    int row = tid >> 3;
    int c   = tid & 7;
    if (row >= NN) return;

    const uint4* cur  = (const uint4*)g_embs[layer - 1];
    uint4*       next = (uint4*)g_embs[layer];

    int s = __ldg(&g_rowptr[row]);
    int t = __ldg(&g_rowptr[row + 1]);

    float2 s0 = make_float2(0.f, 0.f), s1 = s0, s2 = s0, s3 = s0;

    int e = s;
    for (; e + 4 <= t; e += 4) {
        int2 e0 = __ldg(&g_edges[e + 0]);
        int2 e1 = __ldg(&g_edges[e + 1]);
        int2 e2 = __ldg(&g_edges[e + 2]);
        int2 e3 = __ldg(&g_edges[e + 3]);
        uint4 x0 = __ldg(&cur[e0.x * 8 + c]);
        uint4 x1 = __ldg(&cur[e1.x * 8 + c]);
        uint4 x2 = __ldg(&cur[e2.x * 8 + c]);
        uint4 x3 = __ldg(&cur[e3.x * 8 + c]);
        float v0 = __int_as_float(e0.y), v1 = __int_as_float(e1.y);
        float v2 = __int_as_float(e2.y), v3 = __int_as_float(e3.y);
        float2 f;
        f = __half22float2(u_to_h2(x0.x)); s0.x += v0*f.x; s0.y += v0*f.y;
        f = __half22float2(u_to_h2(x0.y)); s1.x += v0*f.x; s1.y += v0*f.y;
        f = __half22float2(u_to_h2(x0.z)); s2.x += v0*f.x; s2.y += v0*f.y;
        f = __half22float2(u_to_h2(x0.w)); s3.x += v0*f.x; s3.y += v0*f.y;
        f = __half22float2(u_to_h2(x1.x)); s0.x += v1*f.x; s0.y += v1*f.y;
        f = __half22float2(u_to_h2(x1.y)); s1.x += v1*f.x; s1.y += v1*f.y;
        f = __half22float2(u_to_h2(x1.z)); s2.x += v1*f.x; s2.y += v1*f.y;
        f = __half22float2(u_to_h2(x1.w)); s3.x += v1*f.x; s3.y += v1*f.y;
        f = __half22float2(u_to_h2(x2.x)); s0.x += v2*f.x; s0.y += v2*f.y;
        f = __half22float2(u_to_h2(x2.y)); s1.x += v2*f.x; s1.y += v2*f.y;
        f = __half22float2(u_to_h2(x2.z)); s2.x += v2*f.x; s2.y += v2*f.y;
        f = __half22float2(u_to_h2(x2.w)); s3.x += v2*f.x; s3.y += v2*f.y;
        f = __half22float2(u_to_h2(x3.x)); s0.x += v3*f.x; s0.y += v3*f.y;
        f = __half22float2(u_to_h2(x3.y)); s1.x += v3*f.x; s1.y += v3*f.y;
        f = __half22float2(u_to_h2(x3.z)); s2.x += v3*f.x; s2.y += v3*f.y;
        f = __half22float2(u_to_h2(x3.w)); s3.x += v3*f.x; s3.y += v3*f.y;
    }
    for (; e < t; e++) {
        int2 ed = __ldg(&g_edges[e]);
        uint4 x = __ldg(&cur[ed.x * 8 + c]);
        float v = __int_as_float(ed.y);
        float2 f;
        f = __half22float2(u_to_h2(x.x)); s0.x += v*f.x; s0.y += v*f.y;
        f = __half22float2(u_to_h2(x.y)); s1.x += v*f.x; s1.y += v*f.y;
        f = __half22float2(u_to_h2(x.z)); s2.x += v*f.x; s2.y += v*f.y;
        f = __half22float2(u_to_h2(x.w)); s3.x += v*f.x; s3.y += v*f.y;
    }

    bool isU = row < NU;
    float w = sigmoidf(isU ? ulw[layer] : ilw[layer]);
    float omw = 1.0f - w;
    const float4* sdp = isU ? (const float4*)se + (size_t)row * 16 + c * 2
                            : (const float4*)he + (size_t)(row - NU) * 16 + c * 2;
    float4 sa = __ldg(sdp);
    float4 sb = __ldg(sdp + 1);

    uint4 hout;
    hout.x = h2_to_u(__floats2half2_rn(w * s0.x + omw * sa.x, w * s0.y + omw * sa.y));
    hout.y = h2_to_u(__floats2half2_rn(w * s1.x + omw * sa.z, w * s1.y + omw * sa.w));
    hout.z = h2_to_u(__floats2half2_rn(w * s2.x + omw * sb.x, w * s2.y + omw * sb.y));
    hout.w = h2_to_u(__floats2half2_rn(w * s3.x + omw * sb.z, w * s3.y + omw * sb.w));
    next[row * 8 + c] = hout;
}

// ---------------------------------------------------------------------------
// Final: acc[row] = sum of 4 layer tables (on the fly, fp32);
// gamma[b] = dot(acc_u, acc_i) / 16. One warp per pair; lane l owns dims 2l,2l+1.
// ---------------------------------------------------------------------------
__global__ void k_dot(const int* __restrict__ users, const int* __restrict__ items,
                      float* __restrict__ out) {
    int w = (blockIdx.x * blockDim.x + threadIdx.x) >> 5;
    int l = threadIdx.x & 31;
    if (w >= NB) return;
    size_t uo = (size_t)users[w] * 32 + l;          // half2 index within table
    size_t io = (size_t)(NU + items[w]) * 32 + l;
    float ux = 0.f, uy = 0.f, ix = 0.f, iy = 0.f;
    #pragma unroll
    for (int L = 0; L <= NL; L++) {
        float2 fu = __half22float2(((const __half2*)g_embs[L])[uo]);
        float2 fi = __half22float2(((const __half2*)g_embs[L])[io]);
        ux += fu.x; uy += fu.y;
        ix += fi.x; iy += fi.y;
    }
    float s = ux * ix + uy * iy;
    #pragma unroll
    for (int o = 16; o > 0; o >>= 1)
        s += __shfl_down_sync(0xffffffffu, s, o);
    if (l == 0) out[w] = s * (1.0f / 16.0f);
}

extern "C" void kernel_launch(void* const* d_in, const int* in_sizes, int n_in,
                              void* d_out, int out_size) {
    const float* user_emb    = (const float*)d_in[0];
    const float* item_emb    = (const float*)d_in[1];
    const float* symptom_emb = (const float*)d_in[2];
    const float* herb_emb    = (const float*)d_in[3];
    const float* user_lw     = (const float*)d_in[4];
    const float* item_lw     = (const float*)d_in[5];
    const float* edge_val    = (const float*)d_in[6];
    const int*   edge_row    = (const int*)d_in[7];
    const int*   edge_col    = (const int*)d_in[8];
    const int*   users       = (const int*)d_in[9];
    const int*   items       = (const int*)d_in[10];
    float* out = (float*)d_out;

    const int n4 = NN * DD / 4;
    const int TB = 256;
    const int gElem = (n4 + TB - 1) / TB;
    const int gEdge = (NE + TB - 1) / TB;
    const int gRow  = (NN * 8 + TB - 1) / TB;

    k_fuse0<<<gElem, TB>>>(user_emb, item_emb, symptom_emb, herb_emb, user_lw, item_lw);
    k_count<<<gEdge, TB>>>(edge_row);
    k_scan_blocks<<<SCAN_NBLK, SCAN_BS>>>();
    k_scan_tops<<<1, SCAN_BS>>>();
    k_scan_add<<<(NN + TB - 1) / TB, TB>>>();
    k_place<<<gEdge, TB>>>(edge_val, edge_row, edge_col);

    for (int layer = 1; layer <= NL; layer++) {
        k_spmm_fuse<<<gRow, TB>>>(symptom_emb, herb_emb, user_lw, item_lw, layer);
    }
    k_dot<<<(NB * 32 + TB - 1) / TB, TB>>>(users, items, out);
}